// round 7
// baseline (speedup 1.0000x reference)
#include <cuda_runtime.h>
#include <cuda_bf16.h>

// CenterLoss: out = mean_b ||features[b] - centers[labels[b]]||^2
// B = 65536, D = 256, C = 100000, LAMBDA_C = 1.0.
//
// Warp owns 2 consecutive rows; one 256-bit load (ld.global.nc.v4.b64) per
// lane covers 32B -> full 1KB row per warp per instruction; 4 loads
// front-batched (asm volatile order) = 32 dest regs.
// R6 bug fixed: __launch_bounds__(256, 4) was CAPPING occupancy at 67%.
// Now (256, 6) -> 6 blocks/SM, 48 warps/SM, ~100% occ, 42-reg budget
// (kernel needs ~40). More resident warps = more requests in the L1tex/LTS
// queues = higher DRAM utilization; traffic is already compulsory-minimal.
// Centers: L2::evict_last (labels repeat across graph replays).
// Features: L2::evict_first (one-pass 64MB stream).
// Block partial -> last-block-done double reduction; wrapping atomic counter
// self-resets across replays.

#define D 256
#define WARPS_PER_BLOCK 8
#define ROWS_PER_WARP 2
#define NBLOCKS 4096   // 4096 * 8 warps * 2 rows = 65536 = B

__device__ float g_partials[NBLOCKS];
__device__ unsigned int g_ctr = 0;

struct V8 { unsigned long long u[4]; };

// Streamed 256-bit load (features: one-pass, evict first)
__device__ __forceinline__ V8 ld_stream(const void* p) {
    V8 v;
    asm volatile("ld.global.nc.L1::evict_first.L2::evict_first.v4.b64 {%0,%1,%2,%3}, [%4];"
                 : "=l"(v.u[0]), "=l"(v.u[1]), "=l"(v.u[2]), "=l"(v.u[3]) : "l"(p));
    return v;
}
// Sticky 256-bit load (centers: keep in L2 across replays)
__device__ __forceinline__ V8 ld_sticky(const void* p) {
    V8 v;
    asm volatile("ld.global.nc.L2::evict_last.v4.b64 {%0,%1,%2,%3}, [%4];"
                 : "=l"(v.u[0]), "=l"(v.u[1]), "=l"(v.u[2]), "=l"(v.u[3]) : "l"(p));
    return v;
}

// s += sum((a-b)^2) over the 8 packed floats
__device__ __forceinline__ float sq8(const V8& a, const V8& b, float s) {
    #pragma unroll
    for (int i = 0; i < 4; i++) {
        float2 af = *reinterpret_cast<const float2*>(&a.u[i]);
        float2 bf = *reinterpret_cast<const float2*>(&b.u[i]);
        float d0 = af.x - bf.x; s = fmaf(d0, d0, s);
        float d1 = af.y - bf.y; s = fmaf(d1, d1, s);
    }
    return s;
}

__global__ __launch_bounds__(WARPS_PER_BLOCK * 32, 6)   // 6 blocks/SM -> 48 warps/SM
void center_loss_fused(const float* __restrict__ feat,
                       const int* __restrict__ labels,
                       const float* __restrict__ centers,
                       float* __restrict__ out, int B) {
    const int warp = threadIdx.x >> 5;
    const int lane = threadIdx.x & 31;
    const int row0 = (blockIdx.x * WARPS_PER_BLOCK + warp) * ROWS_PER_WARP;

    // One broadcast int2 load: labels for both rows of this warp.
    const int2 lab = *reinterpret_cast<const int2*>(labels + row0);

    // Each lane owns bytes [lane*32, lane*32+32) of each 1KB row.
    const char* fbase = reinterpret_cast<const char*>(feat) + (size_t)row0 * D * 4 + lane * 32;
    const char* cbase = reinterpret_cast<const char*>(centers) + lane * 32;

    const void* c0 = cbase + (size_t)lab.x * (D * 4);
    const void* c1 = cbase + (size_t)lab.y * (D * 4);
    const void* f0 = fbase;
    const void* f1 = fbase + D * 4;

    // 4 loads front-batched (asm volatile preserves issue order).
    V8 b0 = ld_sticky(c0);
    V8 b1 = ld_sticky(c1);
    V8 a0 = ld_stream(f0);
    V8 a1 = ld_stream(f1);

    float s0 = sq8(a0, b0, 0.0f);
    float s1 = sq8(a1, b1, 0.0f);
    float acc = s0 + s1;

    // Warp reduction (fixed tree -> deterministic)
    #pragma unroll
    for (int o = 16; o > 0; o >>= 1)
        acc += __shfl_xor_sync(0xFFFFFFFFu, acc, o);

    __shared__ float s[WARPS_PER_BLOCK];
    __shared__ bool is_last;
    if (lane == 0) s[warp] = acc;
    __syncthreads();

    if (threadIdx.x == 0) {
        float t = 0.0f;
        #pragma unroll
        for (int i = 0; i < WARPS_PER_BLOCK; i++) t += s[i];
        g_partials[blockIdx.x] = t;
        __threadfence();
        unsigned int old = atomicInc(&g_ctr, gridDim.x - 1);  // wraps -> replay-safe
        is_last = (old == gridDim.x - 1);
    }
    __syncthreads();

    if (!is_last) return;

    // Last block: deterministic double-precision reduction of 4096 partials.
    __shared__ double sd[256];
    const volatile float* vp = g_partials;
    double t = 0.0;
    #pragma unroll 4
    for (int i = threadIdx.x; i < NBLOCKS; i += 256)
        t += (double)vp[i];
    sd[threadIdx.x] = t;
    __syncthreads();
    #pragma unroll
    for (int stride = 128; stride > 0; stride >>= 1) {
        if (threadIdx.x < stride) sd[threadIdx.x] += sd[threadIdx.x + stride];
        __syncthreads();
    }
    if (threadIdx.x == 0)
        out[0] = (float)(sd[0] / (double)B);   // LAMBDA_C = 1.0
}

extern "C" void kernel_launch(void* const* d_in, const int* in_sizes, int n_in,
                              void* d_out, int out_size) {
    const float* feat    = (const float*)d_in[0];
    const int*   labels  = (const int*)d_in[1];
    const float* centers = (const float*)d_in[2];
    float*       out     = (float*)d_out;

    const int B = in_sizes[1];   // 65536

    center_loss_fused<<<NBLOCKS, WARPS_PER_BLOCK * 32>>>(feat, labels, centers, out, B);
}

// round 8
// speedup vs baseline: 1.2262x; 1.2262x over previous
#include <cuda_runtime.h>
#include <cuda_bf16.h>

// CenterLoss: out = mean_b ||features[b] - centers[labels[b]]||^2
// B = 65536, D = 256, C = 100000, LAMBDA_C = 1.0.
//
// R8: software-pipelined. Prior rounds all pulsed: 4KB burst -> full DRAM
// latency drain -> barrier/atomic epilogue -> block exit. Now each warp owns
// 8 consecutive rows, preloads all 8 labels (2x int4), and runs a depth-2
// register ring: stage j+1's two 256-bit loads (feature row + gathered
// center row, 1KB each per warp) are in flight while stage j is consumed.
// Continuous load issue, 8x fewer block epilogues (1024 blocks).
// Centers: L2::evict_last (labels repeat across graph replays -> resident).
// Features: L2::evict_first (one-pass 64MB stream).
// Block partial -> last-block-done double reduction; wrapping atomic counter
// self-resets across replays.

#define D 256
#define WARPS_PER_BLOCK 8
#define ROWS_PER_WARP 8
#define NBLOCKS 1024   // 1024 * 8 warps * 8 rows = 65536 = B

__device__ float g_partials[NBLOCKS];
__device__ unsigned int g_ctr = 0;

struct V8 { unsigned long long u[4]; };

// Streamed 256-bit load (features: one-pass, evict first)
__device__ __forceinline__ V8 ld_stream(const void* p) {
    V8 v;
    asm volatile("ld.global.nc.L1::evict_first.L2::evict_first.v4.b64 {%0,%1,%2,%3}, [%4];"
                 : "=l"(v.u[0]), "=l"(v.u[1]), "=l"(v.u[2]), "=l"(v.u[3]) : "l"(p));
    return v;
}
// Sticky 256-bit load (centers: keep in L2 across replays)
__device__ __forceinline__ V8 ld_sticky(const void* p) {
    V8 v;
    asm volatile("ld.global.nc.L2::evict_last.v4.b64 {%0,%1,%2,%3}, [%4];"
                 : "=l"(v.u[0]), "=l"(v.u[1]), "=l"(v.u[2]), "=l"(v.u[3]) : "l"(p));
    return v;
}

// s += sum((a-b)^2) over the 8 packed floats
__device__ __forceinline__ float sq8(const V8& a, const V8& b, float s) {
    #pragma unroll
    for (int i = 0; i < 4; i++) {
        float2 af = *reinterpret_cast<const float2*>(&a.u[i]);
        float2 bf = *reinterpret_cast<const float2*>(&b.u[i]);
        float d0 = af.x - bf.x; s = fmaf(d0, d0, s);
        float d1 = af.y - bf.y; s = fmaf(d1, d1, s);
    }
    return s;
}

__global__ __launch_bounds__(WARPS_PER_BLOCK * 32)
void center_loss_fused(const float* __restrict__ feat,
                       const int* __restrict__ labels,
                       const float* __restrict__ centers,
                       float* __restrict__ out, int B) {
    const int warp = threadIdx.x >> 5;
    const int lane = threadIdx.x & 31;
    const int row0 = (blockIdx.x * WARPS_PER_BLOCK + warp) * ROWS_PER_WARP;

    // Preload all 8 labels for this warp (two broadcast int4 loads).
    const int4 labA = *reinterpret_cast<const int4*>(labels + row0);
    const int4 labB = *reinterpret_cast<const int4*>(labels + row0 + 4);
    int labs[8] = { labA.x, labA.y, labA.z, labA.w, labB.x, labB.y, labB.z, labB.w };

    // Each lane owns bytes [lane*32, lane*32+32) of each 1KB row.
    const char* fbase = reinterpret_cast<const char*>(feat) + (size_t)row0 * (D * 4) + lane * 32;
    const char* cbase = reinterpret_cast<const char*>(centers) + lane * 32;

    V8 fa[2], ca[2];

    // Prologue: issue stage 0 loads.
    fa[0] = ld_stream(fbase);
    ca[0] = ld_sticky(cbase + (size_t)labs[0] * (D * 4));

    float acc = 0.0f;
    #pragma unroll
    for (int j = 0; j < ROWS_PER_WARP; j++) {
        const int cur = j & 1, nxt = cur ^ 1;
        if (j + 1 < ROWS_PER_WARP) {
            // Issue next stage's loads BEFORE consuming current stage.
            fa[nxt] = ld_stream(fbase + (size_t)(j + 1) * (D * 4));
            ca[nxt] = ld_sticky(cbase + (size_t)labs[j + 1] * (D * 4));
        }
        acc = sq8(fa[cur], ca[cur], acc);
    }

    // Warp reduction (fixed tree -> deterministic)
    #pragma unroll
    for (int o = 16; o > 0; o >>= 1)
        acc += __shfl_xor_sync(0xFFFFFFFFu, acc, o);

    __shared__ float s[WARPS_PER_BLOCK];
    __shared__ bool is_last;
    if (lane == 0) s[warp] = acc;
    __syncthreads();

    if (threadIdx.x == 0) {
        float t = 0.0f;
        #pragma unroll
        for (int i = 0; i < WARPS_PER_BLOCK; i++) t += s[i];
        g_partials[blockIdx.x] = t;
        __threadfence();
        unsigned int old = atomicInc(&g_ctr, gridDim.x - 1);  // wraps -> replay-safe
        is_last = (old == gridDim.x - 1);
    }
    __syncthreads();

    if (!is_last) return;

    // Last block: deterministic double-precision reduction of 1024 partials.
    __shared__ double sd[256];
    const volatile float* vp = g_partials;
    double t = 0.0;
    #pragma unroll 4
    for (int i = threadIdx.x; i < NBLOCKS; i += 256)
        t += (double)vp[i];
    sd[threadIdx.x] = t;
    __syncthreads();
    #pragma unroll
    for (int stride = 128; stride > 0; stride >>= 1) {
        if (threadIdx.x < stride) sd[threadIdx.x] += sd[threadIdx.x + stride];
        __syncthreads();
    }
    if (threadIdx.x == 0)
        out[0] = (float)(sd[0] / (double)B);   // LAMBDA_C = 1.0
}

extern "C" void kernel_launch(void* const* d_in, const int* in_sizes, int n_in,
                              void* d_out, int out_size) {
    const float* feat    = (const float*)d_in[0];
    const int*   labels  = (const int*)d_in[1];
    const float* centers = (const float*)d_in[2];
    float*       out     = (float*)d_out;

    const int B = in_sizes[1];   // 65536

    center_loss_fused<<<NBLOCKS, WARPS_PER_BLOCK * 32>>>(feat, labels, centers, out, B);
}

// round 10
// speedup vs baseline: 1.3550x; 1.1050x over previous
#include <cuda_runtime.h>
#include <cuda_bf16.h>
#include <cstdint>

// CenterLoss: out = mean_b ||features[b] - centers[labels[b]]||^2
// B = 65536, D = 256, C = 100000, LAMBDA_C = 1.0.
//
// R10 = R9 with the missing <cstdint> include.
// cp.async pipeline: loads go global->SMEM with NO destination registers, so
// ptxas can't serialize them to save regs (the R3/R5/R6/R8 failure mode).
// Warp owns 16 rows; per stage 4x16B cp.async per lane (1KB feat + 1KB
// gathered center), depth-2 SMEM ring, commit_group/wait_group 1.
// Each lane consumes exactly the bytes it copied (no cross-lane sync).
// L2 policy via createpolicy + cache_hint: centers evict_last (labels repeat
// across graph replays -> L2-resident), features evict_first (one-pass).
// Block partial -> last-block-done double reduction; wrapping atomic counter
// self-resets across replays.

#define D 256
#define ROW_BYTES (D * 4)          // 1024
#define WARPS_PER_BLOCK 8
#define ROWS_PER_WARP 16
#define NBLOCKS 512                // 512 * 8 * 16 = 65536 = B
#define DEPTH 2

__device__ float g_partials[NBLOCKS];
__device__ unsigned int g_ctr = 0;

__device__ __forceinline__ void cp16(uint32_t dst_smem, const void* src, unsigned long long pol) {
    asm volatile("cp.async.cg.shared.global.L2::cache_hint [%0], [%1], 16, %2;"
                 :: "r"(dst_smem), "l"(src), "l"(pol) : "memory");
}

__global__ __launch_bounds__(WARPS_PER_BLOCK * 32)
void center_loss_fused(const float* __restrict__ feat,
                       const int* __restrict__ labels,
                       const float* __restrict__ centers,
                       float* __restrict__ out, int B) {
    // Per-warp double-buffered staging: [feat 1KB | center 1KB] per stage.
    __shared__ __align__(16) char cpbuf[WARPS_PER_BLOCK][DEPTH][2 * ROW_BYTES];

    const int warp = threadIdx.x >> 5;
    const int lane = threadIdx.x & 31;
    const int row0 = (blockIdx.x * WARPS_PER_BLOCK + warp) * ROWS_PER_WARP;

    unsigned long long pol_last, pol_first;
    asm volatile("createpolicy.fractional.L2::evict_last.b64 %0, 1.0;"  : "=l"(pol_last));
    asm volatile("createpolicy.fractional.L2::evict_first.b64 %0, 1.0;" : "=l"(pol_first));

    // Preload all 16 labels (4 broadcast int4 loads).
    int labs[ROWS_PER_WARP];
    #pragma unroll
    for (int q = 0; q < 4; q++) {
        int4 l4 = *reinterpret_cast<const int4*>(labels + row0 + q * 4);
        labs[q * 4 + 0] = l4.x; labs[q * 4 + 1] = l4.y;
        labs[q * 4 + 2] = l4.z; labs[q * 4 + 3] = l4.w;
    }

    const char* fbase = reinterpret_cast<const char*>(feat) + (size_t)row0 * ROW_BYTES;
    const char* cbase = reinterpret_cast<const char*>(centers);
    const uint32_t sbase = (uint32_t)__cvta_generic_to_shared(&cpbuf[warp][0][0]);
    const int lo = lane * 16;

    // Issue one stage's 4 cp.asyncs + commit.
    auto issue = [&](int j) {
        const uint32_t d = sbase + (uint32_t)(j & 1) * (2 * ROW_BYTES);
        const char* fs = fbase + (size_t)j * ROW_BYTES;
        const char* cs = cbase + (size_t)labs[j] * ROW_BYTES;
        cp16(d + lo,                   fs + lo,       pol_first);
        cp16(d + 512 + lo,             fs + 512 + lo, pol_first);
        cp16(d + ROW_BYTES + lo,       cs + lo,       pol_last);
        cp16(d + ROW_BYTES + 512 + lo, cs + 512 + lo, pol_last);
        asm volatile("cp.async.commit_group;" ::: "memory");
    };

    issue(0);

    float acc = 0.0f;
    #pragma unroll
    for (int j = 0; j < ROWS_PER_WARP; j++) {
        if (j + 1 < ROWS_PER_WARP) {
            issue(j + 1);
            asm volatile("cp.async.wait_group 1;" ::: "memory");
        } else {
            asm volatile("cp.async.wait_group 0;" ::: "memory");
        }
        // Consume stage j: lane reads exactly the 2x16B (feat) + 2x16B (cent)
        // it copied itself -> no cross-lane visibility needed.
        const char* d = &cpbuf[warp][j & 1][0];
        float4 a0 = *reinterpret_cast<const float4*>(d + lo);
        float4 a1 = *reinterpret_cast<const float4*>(d + 512 + lo);
        float4 b0 = *reinterpret_cast<const float4*>(d + ROW_BYTES + lo);
        float4 b1 = *reinterpret_cast<const float4*>(d + ROW_BYTES + 512 + lo);
        float t;
        t = a0.x - b0.x; acc = fmaf(t, t, acc);
        t = a0.y - b0.y; acc = fmaf(t, t, acc);
        t = a0.z - b0.z; acc = fmaf(t, t, acc);
        t = a0.w - b0.w; acc = fmaf(t, t, acc);
        t = a1.x - b1.x; acc = fmaf(t, t, acc);
        t = a1.y - b1.y; acc = fmaf(t, t, acc);
        t = a1.z - b1.z; acc = fmaf(t, t, acc);
        t = a1.w - b1.w; acc = fmaf(t, t, acc);
    }

    // Warp reduction (fixed tree -> deterministic)
    #pragma unroll
    for (int o = 16; o > 0; o >>= 1)
        acc += __shfl_xor_sync(0xFFFFFFFFu, acc, o);

    __shared__ float s[WARPS_PER_BLOCK];
    __shared__ bool is_last;
    if (lane == 0) s[warp] = acc;
    __syncthreads();

    if (threadIdx.x == 0) {
        float t = 0.0f;
        #pragma unroll
        for (int i = 0; i < WARPS_PER_BLOCK; i++) t += s[i];
        g_partials[blockIdx.x] = t;
        __threadfence();
        unsigned int old = atomicInc(&g_ctr, gridDim.x - 1);  // wraps -> replay-safe
        is_last = (old == gridDim.x - 1);
    }
    __syncthreads();

    if (!is_last) return;

    // Last block: deterministic double-precision reduction of 512 partials.
    __shared__ double sd[256];
    const volatile float* vp = g_partials;
    double t = 0.0;
    for (int i = threadIdx.x; i < NBLOCKS; i += 256)
        t += (double)vp[i];
    sd[threadIdx.x] = t;
    __syncthreads();
    #pragma unroll
    for (int stride = 128; stride > 0; stride >>= 1) {
        if (threadIdx.x < stride) sd[threadIdx.x] += sd[threadIdx.x + stride];
        __syncthreads();
    }
    if (threadIdx.x == 0)
        out[0] = (float)(sd[0] / (double)B);   // LAMBDA_C = 1.0
}

extern "C" void kernel_launch(void* const* d_in, const int* in_sizes, int n_in,
                              void* d_out, int out_size) {
    const float* feat    = (const float*)d_in[0];
    const int*   labels  = (const int*)d_in[1];
    const float* centers = (const float*)d_in[2];
    float*       out     = (float*)d_out;

    const int B = in_sizes[1];   // 65536

    center_loss_fused<<<NBLOCKS, WARPS_PER_BLOCK * 32>>>(feat, labels, centers, out, B);
}

// round 11
// speedup vs baseline: 1.3573x; 1.0017x over previous
#include <cuda_runtime.h>
#include <cuda_bf16.h>
#include <cstdint>

// CenterLoss: out = mean_b ||features[b] - centers[labels[b]]||^2
// B = 65536, D = 256, C = 100000, LAMBDA_C = 1.0.
//
// R11 = R10 with 2x the grid. R10 hit occ=42% purely from grid size
// (512 blocks / 148 SM = 3.5/SM; resources allow 6/SM). Now 8 rows/warp ->
// 1024 blocks = 6.9/SM -> occupancy toward 100%, more outstanding cp.asyncs.
// cp.async pipeline: global->SMEM, no dest registers -> MLP not register-
// bound. Depth-2 SMEM ring per warp, commit_group/wait_group 1; each lane
// consumes exactly the bytes it copied.
// L2 policy: centers evict_last (labels repeat across graph replays ->
// resident), features evict_first (one-pass stream).
// Block partial -> last-block-done double reduction; wrapping atomic counter
// self-resets across replays.

#define D 256
#define ROW_BYTES (D * 4)          // 1024
#define WARPS_PER_BLOCK 8
#define ROWS_PER_WARP 8
#define NBLOCKS 1024               // 1024 * 8 * 8 = 65536 = B
#define DEPTH 2

__device__ float g_partials[NBLOCKS];
__device__ unsigned int g_ctr = 0;

__device__ __forceinline__ void cp16(uint32_t dst_smem, const void* src, unsigned long long pol) {
    asm volatile("cp.async.cg.shared.global.L2::cache_hint [%0], [%1], 16, %2;"
                 :: "r"(dst_smem), "l"(src), "l"(pol) : "memory");
}

__global__ __launch_bounds__(WARPS_PER_BLOCK * 32)
void center_loss_fused(const float* __restrict__ feat,
                       const int* __restrict__ labels,
                       const float* __restrict__ centers,
                       float* __restrict__ out, int B) {
    // Per-warp double-buffered staging: [feat 1KB | center 1KB] per stage.
    __shared__ __align__(16) char cpbuf[WARPS_PER_BLOCK][DEPTH][2 * ROW_BYTES];

    const int warp = threadIdx.x >> 5;
    const int lane = threadIdx.x & 31;
    const int row0 = (blockIdx.x * WARPS_PER_BLOCK + warp) * ROWS_PER_WARP;

    unsigned long long pol_last, pol_first;
    asm volatile("createpolicy.fractional.L2::evict_last.b64 %0, 1.0;"  : "=l"(pol_last));
    asm volatile("createpolicy.fractional.L2::evict_first.b64 %0, 1.0;" : "=l"(pol_first));

    // Preload all 8 labels (2 broadcast int4 loads).
    int labs[ROWS_PER_WARP];
    #pragma unroll
    for (int q = 0; q < 2; q++) {
        int4 l4 = *reinterpret_cast<const int4*>(labels + row0 + q * 4);
        labs[q * 4 + 0] = l4.x; labs[q * 4 + 1] = l4.y;
        labs[q * 4 + 2] = l4.z; labs[q * 4 + 3] = l4.w;
    }

    const char* fbase = reinterpret_cast<const char*>(feat) + (size_t)row0 * ROW_BYTES;
    const char* cbase = reinterpret_cast<const char*>(centers);
    const uint32_t sbase = (uint32_t)__cvta_generic_to_shared(&cpbuf[warp][0][0]);
    const int lo = lane * 16;

    // Issue one stage's 4 cp.asyncs + commit.
    auto issue = [&](int j) {
        const uint32_t d = sbase + (uint32_t)(j & 1) * (2 * ROW_BYTES);
        const char* fs = fbase + (size_t)j * ROW_BYTES;
        const char* cs = cbase + (size_t)labs[j] * ROW_BYTES;
        cp16(d + lo,                   fs + lo,       pol_first);
        cp16(d + 512 + lo,             fs + 512 + lo, pol_first);
        cp16(d + ROW_BYTES + lo,       cs + lo,       pol_last);
        cp16(d + ROW_BYTES + 512 + lo, cs + 512 + lo, pol_last);
        asm volatile("cp.async.commit_group;" ::: "memory");
    };

    issue(0);

    float acc = 0.0f;
    #pragma unroll
    for (int j = 0; j < ROWS_PER_WARP; j++) {
        if (j + 1 < ROWS_PER_WARP) {
            issue(j + 1);
            asm volatile("cp.async.wait_group 1;" ::: "memory");
        } else {
            asm volatile("cp.async.wait_group 0;" ::: "memory");
        }
        // Consume stage j: lane reads exactly the 2x16B (feat) + 2x16B (cent)
        // it copied itself -> no cross-lane visibility needed.
        const char* d = &cpbuf[warp][j & 1][0];
        float4 a0 = *reinterpret_cast<const float4*>(d + lo);
        float4 a1 = *reinterpret_cast<const float4*>(d + 512 + lo);
        float4 b0 = *reinterpret_cast<const float4*>(d + ROW_BYTES + lo);
        float4 b1 = *reinterpret_cast<const float4*>(d + ROW_BYTES + 512 + lo);
        float t;
        t = a0.x - b0.x; acc = fmaf(t, t, acc);
        t = a0.y - b0.y; acc = fmaf(t, t, acc);
        t = a0.z - b0.z; acc = fmaf(t, t, acc);
        t = a0.w - b0.w; acc = fmaf(t, t, acc);
        t = a1.x - b1.x; acc = fmaf(t, t, acc);
        t = a1.y - b1.y; acc = fmaf(t, t, acc);
        t = a1.z - b1.z; acc = fmaf(t, t, acc);
        t = a1.w - b1.w; acc = fmaf(t, t, acc);
    }

    // Warp reduction (fixed tree -> deterministic)
    #pragma unroll
    for (int o = 16; o > 0; o >>= 1)
        acc += __shfl_xor_sync(0xFFFFFFFFu, acc, o);

    __shared__ float s[WARPS_PER_BLOCK];
    __shared__ bool is_last;
    if (lane == 0) s[warp] = acc;
    __syncthreads();

    if (threadIdx.x == 0) {
        float t = 0.0f;
        #pragma unroll
        for (int i = 0; i < WARPS_PER_BLOCK; i++) t += s[i];
        g_partials[blockIdx.x] = t;
        __threadfence();
        unsigned int old = atomicInc(&g_ctr, gridDim.x - 1);  // wraps -> replay-safe
        is_last = (old == gridDim.x - 1);
    }
    __syncthreads();

    if (!is_last) return;

    // Last block: deterministic double-precision reduction of 1024 partials.
    __shared__ double sd[256];
    const volatile float* vp = g_partials;
    double t = 0.0;
    #pragma unroll 4
    for (int i = threadIdx.x; i < NBLOCKS; i += 256)
        t += (double)vp[i];
    sd[threadIdx.x] = t;
    __syncthreads();
    #pragma unroll
    for (int stride = 128; stride > 0; stride >>= 1) {
        if (threadIdx.x < stride) sd[threadIdx.x] += sd[threadIdx.x + stride];
        __syncthreads();
    }
    if (threadIdx.x == 0)
        out[0] = (float)(sd[0] / (double)B);   // LAMBDA_C = 1.0
}

extern "C" void kernel_launch(void* const* d_in, const int* in_sizes, int n_in,
                              void* d_out, int out_size) {
    const float* feat    = (const float*)d_in[0];
    const int*   labels  = (const int*)d_in[1];
    const float* centers = (const float*)d_in[2];
    float*       out     = (float*)d_out;

    const int B = in_sizes[1];   // 65536

    center_loss_fused<<<NBLOCKS, WARPS_PER_BLOCK * 32>>>(feat, labels, centers, out, B);
}

// round 12
// speedup vs baseline: 1.3756x; 1.0135x over previous
#include <cuda_runtime.h>
#include <cuda_bf16.h>
#include <cstdint>

// CenterLoss: out = mean_b ||features[b] - centers[labels[b]]||^2
// B = 65536, D = 256, C = 100000, LAMBDA_C = 1.0.
//
// R12 = R11 with pipeline DEPTH 2 -> 3 (wait_group 2): each warp keeps TWO
// 2KB stages in flight while consuming a third. R11 showed occupancy is no
// longer binding (70% occ but DRAM% fell to 55%); per-warp outstanding bytes
// were the limiter (depth-2 = only 1 stage in flight). smem 48KB/block ->
// 4 blocks/SM, same ~70% occ, 2x outstanding bytes.
// cp.async: global->SMEM, no dest registers -> MLP not register-bound.
// L2 policy: centers evict_last (labels repeat across graph replays ->
// resident), features evict_first (one-pass stream).
// Block partial -> last-block-done double reduction; wrapping atomic counter
// self-resets across replays.

#define D 256
#define ROW_BYTES (D * 4)          // 1024
#define WARPS_PER_BLOCK 8
#define ROWS_PER_WARP 8
#define NBLOCKS 1024               // 1024 * 8 * 8 = 65536 = B
#define DEPTH 3

__device__ float g_partials[NBLOCKS];
__device__ unsigned int g_ctr = 0;

__device__ __forceinline__ void cp16(uint32_t dst_smem, const void* src, unsigned long long pol) {
    asm volatile("cp.async.cg.shared.global.L2::cache_hint [%0], [%1], 16, %2;"
                 :: "r"(dst_smem), "l"(src), "l"(pol) : "memory");
}

__global__ __launch_bounds__(WARPS_PER_BLOCK * 32)
void center_loss_fused(const float* __restrict__ feat,
                       const int* __restrict__ labels,
                       const float* __restrict__ centers,
                       float* __restrict__ out, int B) {
    // Per-warp triple-buffered staging: [feat 1KB | center 1KB] per stage.
    __shared__ __align__(16) char cpbuf[WARPS_PER_BLOCK][DEPTH][2 * ROW_BYTES];

    const int warp = threadIdx.x >> 5;
    const int lane = threadIdx.x & 31;
    const int row0 = (blockIdx.x * WARPS_PER_BLOCK + warp) * ROWS_PER_WARP;

    unsigned long long pol_last, pol_first;
    asm volatile("createpolicy.fractional.L2::evict_last.b64 %0, 1.0;"  : "=l"(pol_last));
    asm volatile("createpolicy.fractional.L2::evict_first.b64 %0, 1.0;" : "=l"(pol_first));

    // Preload all 8 labels (2 broadcast int4 loads).
    int labs[ROWS_PER_WARP];
    #pragma unroll
    for (int q = 0; q < 2; q++) {
        int4 l4 = *reinterpret_cast<const int4*>(labels + row0 + q * 4);
        labs[q * 4 + 0] = l4.x; labs[q * 4 + 1] = l4.y;
        labs[q * 4 + 2] = l4.z; labs[q * 4 + 3] = l4.w;
    }

    const char* fbase = reinterpret_cast<const char*>(feat) + (size_t)row0 * ROW_BYTES;
    const char* cbase = reinterpret_cast<const char*>(centers);
    const uint32_t sbase = (uint32_t)__cvta_generic_to_shared(&cpbuf[warp][0][0]);
    const int lo = lane * 16;

    // Issue one stage's 4 cp.asyncs + commit. Ring slot = j % DEPTH.
    auto issue = [&](int j) {
        const uint32_t d = sbase + (uint32_t)(j % DEPTH) * (2 * ROW_BYTES);
        const char* fs = fbase + (size_t)j * ROW_BYTES;
        const char* cs = cbase + (size_t)labs[j] * ROW_BYTES;
        cp16(d + lo,                   fs + lo,       pol_first);
        cp16(d + 512 + lo,             fs + 512 + lo, pol_first);
        cp16(d + ROW_BYTES + lo,       cs + lo,       pol_last);
        cp16(d + ROW_BYTES + 512 + lo, cs + 512 + lo, pol_last);
        asm volatile("cp.async.commit_group;" ::: "memory");
    };

    // Prologue: two stages in flight.
    issue(0);
    issue(1);

    float acc = 0.0f;
    #pragma unroll
    for (int j = 0; j < ROWS_PER_WARP; j++) {
        if (j + 2 < ROWS_PER_WARP) {
            issue(j + 2);
            asm volatile("cp.async.wait_group 2;" ::: "memory");
        } else if (j + 1 < ROWS_PER_WARP) {
            asm volatile("cp.async.wait_group 1;" ::: "memory");
        } else {
            asm volatile("cp.async.wait_group 0;" ::: "memory");
        }
        // Consume stage j: lane reads exactly the 2x16B (feat) + 2x16B (cent)
        // it copied itself -> no cross-lane visibility needed.
        const char* d = &cpbuf[warp][j % DEPTH][0];
        float4 a0 = *reinterpret_cast<const float4*>(d + lo);
        float4 a1 = *reinterpret_cast<const float4*>(d + 512 + lo);
        float4 b0 = *reinterpret_cast<const float4*>(d + ROW_BYTES + lo);
        float4 b1 = *reinterpret_cast<const float4*>(d + ROW_BYTES + 512 + lo);
        float t;
        t = a0.x - b0.x; acc = fmaf(t, t, acc);
        t = a0.y - b0.y; acc = fmaf(t, t, acc);
        t = a0.z - b0.z; acc = fmaf(t, t, acc);
        t = a0.w - b0.w; acc = fmaf(t, t, acc);
        t = a1.x - b1.x; acc = fmaf(t, t, acc);
        t = a1.y - b1.y; acc = fmaf(t, t, acc);
        t = a1.z - b1.z; acc = fmaf(t, t, acc);
        t = a1.w - b1.w; acc = fmaf(t, t, acc);
    }

    // Warp reduction (fixed tree -> deterministic)
    #pragma unroll
    for (int o = 16; o > 0; o >>= 1)
        acc += __shfl_xor_sync(0xFFFFFFFFu, acc, o);

    __shared__ float s[WARPS_PER_BLOCK];
    __shared__ bool is_last;
    if (lane == 0) s[warp] = acc;
    __syncthreads();

    if (threadIdx.x == 0) {
        float t = 0.0f;
        #pragma unroll
        for (int i = 0; i < WARPS_PER_BLOCK; i++) t += s[i];
        g_partials[blockIdx.x] = t;
        __threadfence();
        unsigned int old = atomicInc(&g_ctr, gridDim.x - 1);  // wraps -> replay-safe
        is_last = (old == gridDim.x - 1);
    }
    __syncthreads();

    if (!is_last) return;

    // Last block: deterministic double-precision reduction of 1024 partials.
    __shared__ double sd[256];
    const volatile float* vp = g_partials;
    double t = 0.0;
    #pragma unroll 4
    for (int i = threadIdx.x; i < NBLOCKS; i += 256)
        t += (double)vp[i];
    sd[threadIdx.x] = t;
    __syncthreads();
    #pragma unroll
    for (int stride = 128; stride > 0; stride >>= 1) {
        if (threadIdx.x < stride) sd[threadIdx.x] += sd[threadIdx.x + stride];
        __syncthreads();
    }
    if (threadIdx.x == 0)
        out[0] = (float)(sd[0] / (double)B);   // LAMBDA_C = 1.0
}

extern "C" void kernel_launch(void* const* d_in, const int* in_sizes, int n_in,
                              void* d_out, int out_size) {
    const float* feat    = (const float*)d_in[0];
    const int*   labels  = (const int*)d_in[1];
    const float* centers = (const float*)d_in[2];
    float*       out     = (float*)d_out;

    const int B = in_sizes[1];   // 65536

    center_loss_fused<<<NBLOCKS, WARPS_PER_BLOCK * 32>>>(feat, labels, centers, out, B);
}